// round 14
// baseline (speedup 1.0000x reference)
#include <cuda_runtime.h>

#define NMAX 50000
#define EMAX 800000
#define HD   64
#define FIN  128
#define NHEADS 4

// ---------------- scratch (static device memory; no allocs) ----------------
__device__ __align__(16) float d_h   [NMAX * HD];          // dinv-scaled xW1 (gather src)
__device__ __align__(16) float d_h2  [NMAX * HD];          // GCN gather result
__device__ __align__(16) float d_hg  [NMAX * NHEADS * HD]; // GAT features [N,4,64]
__device__ __align__(16) float d_asrc[NMAX * NHEADS];
__device__ __align__(16) float d_adst[NMAX * NHEADS];
__device__ __align__(16) float d_den [NMAX * NHEADS];      // softmax denom (raw sums)
__device__ __align__(16) float d_alpha[EMAX * NHEADS];     // per-edge exp values
__device__ __align__(16) float d_hga [NMAX * HD];          // GAT aggregation
__device__ __align__(16) float d_mean[NMAX * HD];          // SAGE sums
__device__ float d_dinv[NMAX];                             // rsqrt(deg+1)
__device__ int   d_deg [NMAX];                             // in-degree (no self loops)
__device__ int   d_off [NMAX + 1];                         // CSR offsets
__device__ int   d_pos [NMAX];                             // fill cursors
__device__ int2  d_epack[EMAX];                            // CSR entries {src, edge id}

// ---------------- helpers ----------------
__device__ __forceinline__ float lrelu(float x) { return x > 0.f ? x : 0.2f * x; }

__device__ __forceinline__ void red_add_v4(float4* p, float4 v) {
    asm volatile("red.global.add.v4.f32 [%0], {%1, %2, %3, %4};"
                 :: "l"(p), "f"(v.x), "f"(v.y), "f"(v.z), "f"(v.w) : "memory");
}

__device__ __forceinline__ int clampi(int v, int n) {
    return ((unsigned)v >= (unsigned)n) ? 0 : v;
}

// ---------------- CSR construction ----------------

__global__ void k_zero_deg(int n) {
    int i = blockIdx.x * blockDim.x + threadIdx.x;
    if (i < n) d_deg[i] = 0;
}

// in-degree count straight off the input edge list
__global__ void k_count(const int* __restrict__ col0, int e, int n) {
    int i = blockIdx.x * blockDim.x + threadIdx.x;
    if (i < e) atomicAdd(&d_deg[clampi(col0[i], n)], 1);
}

// single-block exclusive scan of d_deg -> d_off; also d_pos=0, d_dinv
__global__ void __launch_bounds__(1024) k_scan(int n) {
    __shared__ int ss[1024];
    int tid = threadIdx.x;
    int per = (n + 1023) >> 10;
    int start = tid * per;
    int end = min(start + per, n);
    int s = 0;
    for (int i = start; i < end; i++) s += d_deg[i];
    ss[tid] = s;
    __syncthreads();
    for (int off = 1; off < 1024; off <<= 1) {
        int v = (tid >= off) ? ss[tid - off] : 0;
        __syncthreads();
        ss[tid] += v;
        __syncthreads();
    }
    int run = (tid == 0) ? 0 : ss[tid - 1];
    for (int i = start; i < end; i++) {
        int d = d_deg[i];
        d_off[i] = run;
        d_pos[i] = 0;
        d_dinv[i] = rsqrtf((float)d + 1.0f);
        run += d;
    }
    if (tid == 1023) d_off[n] = run;
}

__global__ void k_fill(const int* __restrict__ row0, const int* __restrict__ col0,
                       int e, int n) {
    int i = blockIdx.x * blockDim.x + threadIdx.x;
    if (i < e) {
        int r = clampi(row0[i], n);
        int c = clampi(col0[i], n);
        int slot = atomicAdd(&d_pos[c], 1);
        d_epack[d_off[c] + slot] = make_int2(r, i);
    }
}

// ---------------- GCN GEMM: d_h = dinv[row]*(x@W1) ----------------
// 256 threads: j0 in {0..7} -> 8 consecutive cols (2 float4 W loads), 32 rows/block, RPT=4.
__global__ void k_gemm_gcn(const float* __restrict__ A, const float* __restrict__ W, int n) {
    const int K = FIN;
    const int ROWS = 32;
    __shared__ float xs[ROWS][K];
    int tid = threadIdx.x;
    int j0  = tid & 7;           // 8 col groups of 8
    int sg  = tid >> 3;          // 0..31 -> rows sg (RPT=1? no: 32 groups x 1 row? )
    // RPT: each sg handles 1 row... that's 32 rows, 32 FFMA*... wait need 4 rows each?
    // Layout: 256 threads = 8 colgroups x 32 row-sgs; ROWS=32 -> each sg owns exactly 1 row.
    // Per k: 2 LDG (W) + 1 LDS (x) + 16 FFMA? Not better. Use RPT=4 over 32 rows: sg 0..7.
    // Redefine: j0 = tid & 31 is wrong; stick with 8 groups x 8 sgs x RPT=4 rows = 32 rows.
    j0 = tid & 7;
    sg = tid >> 3;               // 0..31
    int sg4 = sg & 7;            // row group 0..7 (RPT=4)
    int dummy = sg >> 3;         // 0..3 replicate over k-quarters? No — keep simple split:
    // 64 threads cover (8 colgroups x 8 rowgroups); we have 256 -> split K into 4 chunks.
    int kq = sg >> 3;            // 0..3: k-quarter
    long long base = (long long)blockIdx.x * ROWS;
    {
        const int T4 = ROWS * (K / 4);
        for (int i4 = tid; i4 < T4; i4 += 256) {
            long long row = base + i4 / (K / 4);
            int col4 = i4 % (K / 4);
            reinterpret_cast<float4*>(xs)[i4] =
                (row < n) ? __ldg(reinterpret_cast<const float4*>(A + row * K) + col4)
                          : make_float4(0.f, 0.f, 0.f, 0.f);
        }
    }
    __syncthreads();
    // each thread: k in [kq*32, kq*32+32), rows sg4*4..+3, cols j0*8..+7
    float4 a0[4], a1[4];
#pragma unroll
    for (int r = 0; r < 4; r++) {
        a0[r] = make_float4(0.f, 0.f, 0.f, 0.f);
        a1[r] = make_float4(0.f, 0.f, 0.f, 0.f);
    }
    int k0 = kq * 32;
#pragma unroll 4
    for (int kk = 0; kk < 32; kk++) {
        int k = k0 + kk;
        float4 w0 = __ldg(reinterpret_cast<const float4*>(W + k * HD) + j0 * 2);
        float4 w1 = __ldg(reinterpret_cast<const float4*>(W + k * HD) + j0 * 2 + 1);
#pragma unroll
        for (int r = 0; r < 4; r++) {
            float xv = xs[sg4 * 4 + r][k];
            a0[r].x += xv * w0.x; a0[r].y += xv * w0.y; a0[r].z += xv * w0.z; a0[r].w += xv * w0.w;
            a1[r].x += xv * w1.x; a1[r].y += xv * w1.y; a1[r].z += xv * w1.z; a1[r].w += xv * w1.w;
        }
    }
    // reduce k-quarters via smem (reuse xs): 4 partials per (row,colgroup)
    __syncthreads();
    float* red = &xs[0][0];   // size 32*128 floats = 16KB, need 32rows*64cols = 2048 floats per quarter pass
    // accumulate quarters serially: quarter 0 writes, others add
    for (int qq = 0; qq < 4; qq++) {
        if (kq == qq) {
#pragma unroll
            for (int r = 0; r < 4; r++) {
                float* dst = red + (sg4 * 4 + r) * 64 + j0 * 8;
                if (qq == 0) {
                    dst[0] = a0[r].x; dst[1] = a0[r].y; dst[2] = a0[r].z; dst[3] = a0[r].w;
                    dst[4] = a1[r].x; dst[5] = a1[r].y; dst[6] = a1[r].z; dst[7] = a1[r].w;
                } else {
                    dst[0] += a0[r].x; dst[1] += a0[r].y; dst[2] += a0[r].z; dst[3] += a0[r].w;
                    dst[4] += a1[r].x; dst[5] += a1[r].y; dst[6] += a1[r].z; dst[7] += a1[r].w;
                }
            }
        }
        __syncthreads();
    }
    // write out: 256 threads cover 32 rows x 16 float4s
    for (int i4 = tid; i4 < ROWS * 16; i4 += 256) {
        long long row = base + i4 / 16;
        if (row < n) {
            int q = i4 & 15;
            float4 v = reinterpret_cast<const float4*>(red)[i4];
            float dv = __ldg(&d_dinv[row]);
            reinterpret_cast<float4*>(d_h)[row * 16 + q] =
                make_float4(v.x * dv, v.y * dv, v.z * dv, v.w * dv);
        }
    }
}

// GCN gather (CSR): h2[g] = h[g] + sum_{r in in(g)} h[r]   (no atomics)
__global__ void k_gcn_gather(int n) {
    int g = blockIdx.x * 16 + (threadIdx.x >> 4);
    int q = threadIdx.x & 15;
    if (g >= n) return;
    int o0 = d_off[g], o1 = d_off[g + 1];
    float4 acc = reinterpret_cast<const float4*>(d_h)[g * 16 + q];
    for (int o = o0; o < o1; o++) {
        int r = __ldg(&d_epack[o].x);
        float4 v = __ldg(reinterpret_cast<const float4*>(d_h) + r * 16 + q);
        acc.x += v.x; acc.y += v.y; acc.z += v.z; acc.w += v.w;
    }
    reinterpret_cast<float4*>(d_h2)[g * 16 + q] = acc;
}

// ---------------- GAT GEMM (fused relu(dinv*h2+b1)) ----------------
__global__ void k_gemm_gat(const float* __restrict__ Wg, const float* __restrict__ b1, int n) {
    const int K = HD, M = NHEADS * HD, JT = 64, SG = 4, RPT = 8;
    const int ROWS = SG * RPT;                       // 32
    __shared__ float xs[ROWS][K];
    int tid = threadIdx.x;
    int j0  = tid % JT;
    int sg  = tid / JT;
    long long base = (long long)blockIdx.x * ROWS;
    {
        const int T4 = ROWS * (K / 4);
        for (int i4 = tid; i4 < T4; i4 += 256) {
            long long row = base + i4 / (K / 4);
            int col4 = i4 % (K / 4);
            float4 v = make_float4(0.f, 0.f, 0.f, 0.f);
            if (row < n) {
                float4 h2v = __ldg(reinterpret_cast<const float4*>(d_h2) + row * 16 + col4);
                float4 bv  = __ldg(reinterpret_cast<const float4*>(b1) + col4);
                float dv = __ldg(&d_dinv[row]);
                v.x = fmaxf(dv * h2v.x + bv.x, 0.f);
                v.y = fmaxf(dv * h2v.y + bv.y, 0.f);
                v.z = fmaxf(dv * h2v.z + bv.z, 0.f);
                v.w = fmaxf(dv * h2v.w + bv.w, 0.f);
            }
            reinterpret_cast<float4*>(xs)[i4] = v;
        }
    }
    __syncthreads();
    float4 acc[RPT];
#pragma unroll
    for (int r = 0; r < RPT; r++) acc[r] = make_float4(0.f, 0.f, 0.f, 0.f);
#pragma unroll 4
    for (int k = 0; k < K; k++) {
        float4 wv = __ldg(reinterpret_cast<const float4*>(Wg + k * M) + j0);
#pragma unroll
        for (int r = 0; r < RPT; r++) {
            float xv = xs[sg * RPT + r][k];
            acc[r].x += xv * wv.x;
            acc[r].y += xv * wv.y;
            acc[r].z += xv * wv.z;
            acc[r].w += xv * wv.w;
        }
    }
#pragma unroll
    for (int r = 0; r < RPT; r++) {
        long long row = base + sg * RPT + r;
        if (row < n)
            reinterpret_cast<float4*>(d_hg)[row * 64 + j0] = acc[r];
    }
}

// per-(node,head) attention logits + denom init = exp(self logit)
__global__ void k_att(const float* __restrict__ att_src,
                      const float* __restrict__ att_dst, int n) {
    long long w = (long long)(blockIdx.x * blockDim.x + threadIdx.x) >> 5;
    int lane = threadIdx.x & 31;
    long long total = (long long)n * NHEADS;
    long long stride = ((long long)gridDim.x * blockDim.x) >> 5;
    for (; w < total; w += stride) {
        int node = (int)(w >> 2), head = (int)(w & 3);
        const float* hgp = &d_hg[(long long)node * (NHEADS * HD) + head * HD];
        float s = hgp[lane] * __ldg(&att_src[head * HD + lane]) +
                  hgp[lane + 32] * __ldg(&att_src[head * HD + lane + 32]);
        float t = hgp[lane] * __ldg(&att_dst[head * HD + lane]) +
                  hgp[lane + 32] * __ldg(&att_dst[head * HD + lane + 32]);
#pragma unroll
        for (int o = 16; o; o >>= 1) {
            s += __shfl_down_sync(0xffffffffu, s, o);
            t += __shfl_down_sync(0xffffffffu, t, o);
        }
        if (lane == 0) {
            d_asrc[w] = s;
            d_adst[w] = t;
            d_den[w]  = expf(lrelu(s + t));
        }
    }
}

// per-edge ex = exp(lrelu(asrc[r]+adst[c])): store + vector-RED into denom
__global__ void k_den_edges(const int* __restrict__ row0, const int* __restrict__ col0,
                            int e, int n) {
    int i = blockIdx.x * blockDim.x + threadIdx.x;
    if (i < e) {
        int r = clampi(row0[i], n), c = clampi(col0[i], n);
        const float4 as = reinterpret_cast<const float4*>(d_asrc)[r];
        const float4 ad = reinterpret_cast<const float4*>(d_adst)[c];
        float4 ex;
        ex.x = expf(lrelu(as.x + ad.x));
        ex.y = expf(lrelu(as.y + ad.y));
        ex.z = expf(lrelu(as.z + ad.z));
        ex.w = expf(lrelu(as.w + ad.w));
        reinterpret_cast<float4*>(d_alpha)[i] = ex;
        red_add_v4(&reinterpret_cast<float4*>(d_den)[c], ex);
    }
}

// GAT gather (CSR): hga[g] = sum over {self, in-edges} of per-head weighted hg rows
__global__ void k_gat_gather(int n) {
    int g = blockIdx.x * 16 + (threadIdx.x >> 4);
    int q = threadIdx.x & 15;
    if (g >= n) return;
    const float4 dn = reinterpret_cast<const float4*>(d_den)[g];
    float ix = 0.25f / dn.x, iy = 0.25f / dn.y, iz = 0.25f / dn.z, iw = 0.25f / dn.w;
    const float4 as = reinterpret_cast<const float4*>(d_asrc)[g];
    const float4 ad = reinterpret_cast<const float4*>(d_adst)[g];
    float wx = expf(lrelu(as.x + ad.x)) * ix;
    float wy = expf(lrelu(as.y + ad.y)) * iy;
    float wz = expf(lrelu(as.z + ad.z)) * iz;
    float ww = expf(lrelu(as.w + ad.w)) * iw;
    const float4* hg4 = reinterpret_cast<const float4*>(d_hg);
    long long sbase = (long long)g * 64;
    float4 a = hg4[sbase + 0 * 16 + q];
    float4 b = hg4[sbase + 1 * 16 + q];
    float4 cc = hg4[sbase + 2 * 16 + q];
    float4 dd = hg4[sbase + 3 * 16 + q];
    float4 acc;
    acc.x = wx * a.x + wy * b.x + wz * cc.x + ww * dd.x;
    acc.y = wx * a.y + wy * b.y + wz * cc.y + ww * dd.y;
    acc.z = wx * a.z + wy * b.z + wz * cc.z + ww * dd.z;
    acc.w = wx * a.w + wy * b.w + wz * cc.w + ww * dd.w;
    int o0 = d_off[g], o1 = d_off[g + 1];
    for (int o = o0; o < o1; o++) {
        int2 pk = __ldg(&d_epack[o]);
        const float4 ex = __ldg(reinterpret_cast<const float4*>(d_alpha) + pk.y);
        float ex0 = ex.x * ix, ex1 = ex.y * iy, ex2 = ex.z * iz, ex3 = ex.w * iw;
        long long base = (long long)pk.x * 64;
        float4 ra = hg4[base + 0 * 16 + q];
        float4 rb = hg4[base + 1 * 16 + q];
        float4 rc = hg4[base + 2 * 16 + q];
        float4 rd = hg4[base + 3 * 16 + q];
        acc.x += ex0 * ra.x + ex1 * rb.x + ex2 * rc.x + ex3 * rd.x;
        acc.y += ex0 * ra.y + ex1 * rb.y + ex2 * rc.y + ex3 * rd.y;
        acc.z += ex0 * ra.z + ex1 * rb.z + ex2 * rc.z + ex3 * rd.z;
        acc.w += ex0 * ra.w + ex1 * rb.w + ex2 * rc.w + ex3 * rd.w;
    }
    reinterpret_cast<float4*>(d_hga)[g * 16 + q] = acc;
}

// SAGE gather (CSR): mean[g] = sum_{r in in(g)} relu(hga[r]+bg)
__global__ void k_sage_gather(const float* __restrict__ bg, int n) {
    int g = blockIdx.x * 16 + (threadIdx.x >> 4);
    int q = threadIdx.x & 15;
    if (g >= n) return;
    float4 bv = __ldg(reinterpret_cast<const float4*>(bg) + q);
    float4 acc = make_float4(0.f, 0.f, 0.f, 0.f);
    int o0 = d_off[g], o1 = d_off[g + 1];
    for (int o = o0; o < o1; o++) {
        int r = __ldg(&d_epack[o].x);
        float4 h = __ldg(reinterpret_cast<const float4*>(d_hga) + r * 16 + q);
        acc.x += fmaxf(h.x + bv.x, 0.f);
        acc.y += fmaxf(h.y + bv.y, 0.f);
        acc.z += fmaxf(h.z + bv.z, 0.f);
        acc.w += fmaxf(h.w + bv.w, 0.f);
    }
    reinterpret_cast<float4*>(d_mean)[g * 16 + q] = acc;
}

// final: emb = (mean/deg)@Wl + bl + relu(hga+bg)@Wr ; MLP heads ; outputs
__global__ void k_final(const float* __restrict__ Wl, const float* __restrict__ bl,
                        const float* __restrict__ Wr, const float* __restrict__ bg,
                        const float* __restrict__ a1w, const float* __restrict__ a1b,
                        const float* __restrict__ a2w, const float* __restrict__ a2b,
                        const float* __restrict__ r1w, const float* __restrict__ r1b,
                        const float* __restrict__ r2w, const float* __restrict__ r2b,
                        float* __restrict__ out_emb, float* __restrict__ out_an,
                        float* __restrict__ out_risk, int n) {
    __shared__ float Wls[HD * HD], Wrs[HD * HD];
    __shared__ float ms[4][HD], hs[4][HD], embs[4][HD];
    int tid = threadIdx.x;
    for (int i = tid; i < HD * HD; i += blockDim.x) {
        Wls[i] = Wl[i];
        Wrs[i] = Wr[i];
    }
    int sub = tid >> 6, j = tid & 63;
    int lane = tid & 31, wp = tid >> 5;
    int nd = wp >> 1, hd = wp & 1;
    for (long long base = (long long)blockIdx.x * 4; base < n;
         base += (long long)gridDim.x * 4) {
        int node = (int)base + sub;
        __syncthreads();
        if (node < n) {
            float inv = 1.f / fmaxf((float)d_deg[node], 1.f);
            ms[sub][j] = d_mean[node * HD + j] * inv;
            hs[sub][j] = fmaxf(d_hga[node * HD + j] + bg[j], 0.f);
        }
        __syncthreads();
        if (node < n) {
            float acc = bl[j];
#pragma unroll 16
            for (int k = 0; k < HD; k++)
                acc += ms[sub][k] * Wls[k * HD + j] + hs[sub][k] * Wrs[k * HD + j];
            embs[sub][j] = acc;
            out_emb[(long long)node * HD + j] = acc;
        }
        __syncthreads();
        int node2 = (int)base + nd;
        if (node2 < n) {
            const float* W1p = hd ? r1w : a1w;
            float acc = hd ? __ldg(&r1b[lane]) : __ldg(&a1b[lane]);
#pragma unroll 16
            for (int k = 0; k < HD; k++)
                acc += embs[nd][k] * __ldg(&W1p[k * 32 + lane]);
            acc = fmaxf(acc, 0.f) * (hd ? __ldg(&r2w[lane]) : __ldg(&a2w[lane]));
#pragma unroll
            for (int o = 16; o; o >>= 1) acc += __shfl_down_sync(0xffffffffu, acc, o);
            if (lane == 0) {
                float b2 = hd ? __ldg(&r2b[0]) : __ldg(&a2b[0]);
                float v = 1.f / (1.f + expf(-(acc + b2)));
                if (hd) out_risk[node2] = v;
                else    out_an[node2] = v;
            }
        }
    }
}

// ---------------- launcher ----------------
extern "C" void kernel_launch(void* const* d_in, const int* in_sizes, int n_in,
                              void* d_out, int out_size) {
    const float* x   = (const float*)d_in[0];
    const int*   ei  = (const int*)d_in[1];   // int32 (JAX x64 disabled)
    const float* W1  = (const float*)d_in[2];
    const float* b1  = (const float*)d_in[3];
    const float* Wg  = (const float*)d_in[4];
    const float* ats = (const float*)d_in[5];
    const float* atd = (const float*)d_in[6];
    const float* bg  = (const float*)d_in[7];
    const float* Wl  = (const float*)d_in[8];
    const float* bl  = (const float*)d_in[9];
    const float* Wr  = (const float*)d_in[10];
    const float* a1w = (const float*)d_in[11];
    const float* a1b = (const float*)d_in[12];
    const float* a2w = (const float*)d_in[13];
    const float* a2b = (const float*)d_in[14];
    const float* r1w = (const float*)d_in[15];
    const float* r1b = (const float*)d_in[16];
    const float* r2w = (const float*)d_in[17];
    const float* r2b = (const float*)d_in[18];

    int n = in_sizes[0] / FIN;
    int e = in_sizes[1] / 2;
    const int* row0 = ei;
    const int* col0 = ei + e;

    float* out      = (float*)d_out;
    float* out_emb  = out;
    float* out_an   = out + (long long)n * HD;
    float* out_risk = out_an + n;

    const int B = 256;
    int gN  = (n + B - 1) / B;
    int gE  = (e + B - 1) / B;
    int gG  = (n + 15) / 16;

    // CSR build
    k_zero_deg<<<gN, B>>>(n);
    k_count<<<gE, B>>>(col0, e, n);
    k_scan<<<1, 1024>>>(n);
    k_fill<<<gE, B>>>(row0, col0, e, n);

    // GCN
    k_gemm_gcn<<<(n + 31) / 32, 256>>>(x, W1, n);
    k_gcn_gather<<<gG, B>>>(n);

    // GAT
    k_gemm_gat<<<(n + 31) / 32, 256>>>(Wg, b1, n);
    k_att<<<(n * NHEADS * 32 + B - 1) / B, B>>>(ats, atd, n);
    k_den_edges<<<gE, B>>>(row0, col0, e, n);
    k_gat_gather<<<gG, B>>>(n);

    // SAGE
    k_sage_gather<<<gG, B>>>(bg, n);

    // emb + heads
    k_final<<<(n + 3) / 4, B>>>(Wl, bl, Wr, bg, a1w, a1b, a2w, a2b,
                                r1w, r1b, r2w, r2b,
                                out_emb, out_an, out_risk, n);
}

// round 15
// speedup vs baseline: 1.5706x; 1.5706x over previous
#include <cuda_runtime.h>

#define NMAX 50000
#define EMAX 800000
#define HD   64
#define FIN  128
#define NHEADS 4

// ---------------- scratch (static device memory; no allocs) ----------------
__device__ __align__(16) float d_h   [NMAX * HD];          // dinv-scaled xW1 (gather src)
__device__ __align__(16) float d_h2  [NMAX * HD];          // GCN gather result
__device__ __align__(16) float d_hg  [NMAX * NHEADS * HD]; // GAT features [N,4,64]
__device__ __align__(16) float d_asrc[NMAX * NHEADS];
__device__ __align__(16) float d_adst[NMAX * NHEADS];
__device__ __align__(16) float d_den [NMAX * NHEADS];      // softmax denom (raw sums)
__device__ __align__(16) float d_alpha[EMAX * NHEADS];     // per-edge exp values
__device__ __align__(16) float d_hga [NMAX * HD];          // GAT aggregation
__device__ __align__(16) float d_mean[NMAX * HD];          // SAGE sums
__device__ float d_dinv[NMAX];                             // rsqrt(deg+1)
__device__ int   d_deg [NMAX];                             // in-degree (no self loops)
__device__ int   d_off [NMAX + 1];                         // CSR offsets
__device__ int   d_pos [NMAX];                             // fill cursors
__device__ int2  d_epack[EMAX];                            // CSR entries {src, edge id}

// ---------------- helpers ----------------
__device__ __forceinline__ float lrelu(float x) { return x > 0.f ? x : 0.2f * x; }

__device__ __forceinline__ void red_add_v4(float4* p, float4 v) {
    asm volatile("red.global.add.v4.f32 [%0], {%1, %2, %3, %4};"
                 :: "l"(p), "f"(v.x), "f"(v.y), "f"(v.z), "f"(v.w) : "memory");
}

__device__ __forceinline__ int clampi(int v, int n) {
    return ((unsigned)v >= (unsigned)n) ? 0 : v;
}

// ---------------- CSR construction ----------------

__global__ void k_zero_deg(int n) {
    int i = blockIdx.x * blockDim.x + threadIdx.x;
    if (i < n) d_deg[i] = 0;
}

// in-degree count straight off the input edge list
__global__ void k_count(const int* __restrict__ col0, int e, int n) {
    int i = blockIdx.x * blockDim.x + threadIdx.x;
    if (i < e) atomicAdd(&d_deg[clampi(col0[i], n)], 1);
}

// single-block exclusive scan of d_deg -> d_off; also d_pos=0, d_dinv
__global__ void __launch_bounds__(1024) k_scan(int n) {
    __shared__ int ss[1024];
    int tid = threadIdx.x;
    int per = (n + 1023) >> 10;
    int start = tid * per;
    int end = min(start + per, n);
    int s = 0;
    for (int i = start; i < end; i++) s += d_deg[i];
    ss[tid] = s;
    __syncthreads();
    for (int off = 1; off < 1024; off <<= 1) {
        int v = (tid >= off) ? ss[tid - off] : 0;
        __syncthreads();
        ss[tid] += v;
        __syncthreads();
    }
    int run = (tid == 0) ? 0 : ss[tid - 1];
    for (int i = start; i < end; i++) {
        int d = d_deg[i];
        d_off[i] = run;
        d_pos[i] = 0;
        d_dinv[i] = rsqrtf((float)d + 1.0f);
        run += d;
    }
    if (tid == 1023) d_off[n] = run;
}

__global__ void k_fill(const int* __restrict__ row0, const int* __restrict__ col0,
                       int e, int n) {
    int i = blockIdx.x * blockDim.x + threadIdx.x;
    if (i < e) {
        int r = clampi(row0[i], n);
        int c = clampi(col0[i], n);
        int slot = atomicAdd(&d_pos[c], 1);
        d_epack[d_off[c] + slot] = make_int2(r, i);
    }
}

// ---------------- GCN GEMM (R12 shape): d_h = dinv[row]*(x@W1) ----------------
__global__ void k_gemm_gcn(const float* __restrict__ A, const float* __restrict__ W, int n) {
    const int K = FIN, JT = 16, SG = 16, RPT = 4;
    const int ROWS = SG * RPT;                       // 64
    __shared__ float xs[ROWS][K];
    int tid = threadIdx.x;
    int j0  = tid % JT;
    int sg  = tid / JT;
    long long base = (long long)blockIdx.x * ROWS;
    {
        const int T4 = ROWS * (K / 4);
        for (int i4 = tid; i4 < T4; i4 += 256) {
            long long row = base + i4 / (K / 4);
            int col4 = i4 % (K / 4);
            reinterpret_cast<float4*>(xs)[i4] =
                (row < n) ? __ldg(reinterpret_cast<const float4*>(A + row * K) + col4)
                          : make_float4(0.f, 0.f, 0.f, 0.f);
        }
    }
    __syncthreads();
    float4 acc[RPT];
#pragma unroll
    for (int r = 0; r < RPT; r++) acc[r] = make_float4(0.f, 0.f, 0.f, 0.f);
#pragma unroll 4
    for (int k = 0; k < K; k++) {
        float4 wv = __ldg(reinterpret_cast<const float4*>(W + k * HD) + j0);
#pragma unroll
        for (int r = 0; r < RPT; r++) {
            float xv = xs[sg * RPT + r][k];
            acc[r].x += xv * wv.x;
            acc[r].y += xv * wv.y;
            acc[r].z += xv * wv.z;
            acc[r].w += xv * wv.w;
        }
    }
#pragma unroll
    for (int r = 0; r < RPT; r++) {
        long long row = base + sg * RPT + r;
        if (row < n) {
            float dv = __ldg(&d_dinv[row]);
            reinterpret_cast<float4*>(d_h)[row * 16 + j0] =
                make_float4(acc[r].x * dv, acc[r].y * dv, acc[r].z * dv, acc[r].w * dv);
        }
    }
}

// GCN gather (CSR): h2[g] = h[g] + sum_{r in in(g)} h[r]   (no atomics)
__global__ void k_gcn_gather(int n) {
    int g = blockIdx.x * 16 + (threadIdx.x >> 4);
    int q = threadIdx.x & 15;
    if (g >= n) return;
    int o0 = d_off[g], o1 = d_off[g + 1];
    float4 acc = reinterpret_cast<const float4*>(d_h)[g * 16 + q];
    for (int o = o0; o < o1; o++) {
        int r = __ldg(&d_epack[o].x);
        float4 v = __ldg(reinterpret_cast<const float4*>(d_h) + r * 16 + q);
        acc.x += v.x; acc.y += v.y; acc.z += v.z; acc.w += v.w;
    }
    reinterpret_cast<float4*>(d_h2)[g * 16 + q] = acc;
}

// ---------------- GAT GEMM (fused relu(dinv*h2+b1)) ----------------
__global__ void k_gemm_gat(const float* __restrict__ Wg, const float* __restrict__ b1, int n) {
    const int K = HD, M = NHEADS * HD, JT = 64, SG = 4, RPT = 8;
    const int ROWS = SG * RPT;                       // 32
    __shared__ float xs[ROWS][K];
    int tid = threadIdx.x;
    int j0  = tid % JT;
    int sg  = tid / JT;
    long long base = (long long)blockIdx.x * ROWS;
    {
        const int T4 = ROWS * (K / 4);
        for (int i4 = tid; i4 < T4; i4 += 256) {
            long long row = base + i4 / (K / 4);
            int col4 = i4 % (K / 4);
            float4 v = make_float4(0.f, 0.f, 0.f, 0.f);
            if (row < n) {
                float4 h2v = __ldg(reinterpret_cast<const float4*>(d_h2) + row * 16 + col4);
                float4 bv  = __ldg(reinterpret_cast<const float4*>(b1) + col4);
                float dv = __ldg(&d_dinv[row]);
                v.x = fmaxf(dv * h2v.x + bv.x, 0.f);
                v.y = fmaxf(dv * h2v.y + bv.y, 0.f);
                v.z = fmaxf(dv * h2v.z + bv.z, 0.f);
                v.w = fmaxf(dv * h2v.w + bv.w, 0.f);
            }
            reinterpret_cast<float4*>(xs)[i4] = v;
        }
    }
    __syncthreads();
    float4 acc[RPT];
#pragma unroll
    for (int r = 0; r < RPT; r++) acc[r] = make_float4(0.f, 0.f, 0.f, 0.f);
#pragma unroll 4
    for (int k = 0; k < K; k++) {
        float4 wv = __ldg(reinterpret_cast<const float4*>(Wg + k * M) + j0);
#pragma unroll
        for (int r = 0; r < RPT; r++) {
            float xv = xs[sg * RPT + r][k];
            acc[r].x += xv * wv.x;
            acc[r].y += xv * wv.y;
            acc[r].z += xv * wv.z;
            acc[r].w += xv * wv.w;
        }
    }
#pragma unroll
    for (int r = 0; r < RPT; r++) {
        long long row = base + sg * RPT + r;
        if (row < n)
            reinterpret_cast<float4*>(d_hg)[row * 64 + j0] = acc[r];
    }
}

// per-(node,head) attention logits + denom init = exp(self logit)
__global__ void k_att(const float* __restrict__ att_src,
                      const float* __restrict__ att_dst, int n) {
    long long w = (long long)(blockIdx.x * blockDim.x + threadIdx.x) >> 5;
    int lane = threadIdx.x & 31;
    long long total = (long long)n * NHEADS;
    long long stride = ((long long)gridDim.x * blockDim.x) >> 5;
    for (; w < total; w += stride) {
        int node = (int)(w >> 2), head = (int)(w & 3);
        const float* hgp = &d_hg[(long long)node * (NHEADS * HD) + head * HD];
        float s = hgp[lane] * __ldg(&att_src[head * HD + lane]) +
                  hgp[lane + 32] * __ldg(&att_src[head * HD + lane + 32]);
        float t = hgp[lane] * __ldg(&att_dst[head * HD + lane]) +
                  hgp[lane + 32] * __ldg(&att_dst[head * HD + lane + 32]);
#pragma unroll
        for (int o = 16; o; o >>= 1) {
            s += __shfl_down_sync(0xffffffffu, s, o);
            t += __shfl_down_sync(0xffffffffu, t, o);
        }
        if (lane == 0) {
            d_asrc[w] = s;
            d_adst[w] = t;
            d_den[w]  = expf(lrelu(s + t));
        }
    }
}

// per-edge ex = exp(lrelu(asrc[r]+adst[c])): store + vector-RED into denom
__global__ void k_den_edges(const int* __restrict__ row0, const int* __restrict__ col0,
                            int e, int n) {
    int i = blockIdx.x * blockDim.x + threadIdx.x;
    if (i < e) {
        int r = clampi(row0[i], n), c = clampi(col0[i], n);
        const float4 as = reinterpret_cast<const float4*>(d_asrc)[r];
        const float4 ad = reinterpret_cast<const float4*>(d_adst)[c];
        float4 ex;
        ex.x = expf(lrelu(as.x + ad.x));
        ex.y = expf(lrelu(as.y + ad.y));
        ex.z = expf(lrelu(as.z + ad.z));
        ex.w = expf(lrelu(as.w + ad.w));
        reinterpret_cast<float4*>(d_alpha)[i] = ex;
        red_add_v4(&reinterpret_cast<float4*>(d_den)[c], ex);
    }
}

// GAT gather (CSR): hga[g] = sum over {self, in-edges} of per-head weighted hg rows
__global__ void k_gat_gather(int n) {
    int g = blockIdx.x * 16 + (threadIdx.x >> 4);
    int q = threadIdx.x & 15;
    if (g >= n) return;
    const float4 dn = reinterpret_cast<const float4*>(d_den)[g];
    float ix = 0.25f / dn.x, iy = 0.25f / dn.y, iz = 0.25f / dn.z, iw = 0.25f / dn.w;
    const float4 as = reinterpret_cast<const float4*>(d_asrc)[g];
    const float4 ad = reinterpret_cast<const float4*>(d_adst)[g];
    float wx = expf(lrelu(as.x + ad.x)) * ix;
    float wy = expf(lrelu(as.y + ad.y)) * iy;
    float wz = expf(lrelu(as.z + ad.z)) * iz;
    float ww = expf(lrelu(as.w + ad.w)) * iw;
    const float4* hg4 = reinterpret_cast<const float4*>(d_hg);
    long long sbase = (long long)g * 64;
    float4 a = hg4[sbase + 0 * 16 + q];
    float4 b = hg4[sbase + 1 * 16 + q];
    float4 cc = hg4[sbase + 2 * 16 + q];
    float4 dd = hg4[sbase + 3 * 16 + q];
    float4 acc;
    acc.x = wx * a.x + wy * b.x + wz * cc.x + ww * dd.x;
    acc.y = wx * a.y + wy * b.y + wz * cc.y + ww * dd.y;
    acc.z = wx * a.z + wy * b.z + wz * cc.z + ww * dd.z;
    acc.w = wx * a.w + wy * b.w + wz * cc.w + ww * dd.w;
    int o0 = d_off[g], o1 = d_off[g + 1];
    for (int o = o0; o < o1; o++) {
        int2 pk = __ldg(&d_epack[o]);
        const float4 ex = __ldg(reinterpret_cast<const float4*>(d_alpha) + pk.y);
        float ex0 = ex.x * ix, ex1 = ex.y * iy, ex2 = ex.z * iz, ex3 = ex.w * iw;
        long long base = (long long)pk.x * 64;
        float4 ra = hg4[base + 0 * 16 + q];
        float4 rb = hg4[base + 1 * 16 + q];
        float4 rc = hg4[base + 2 * 16 + q];
        float4 rd = hg4[base + 3 * 16 + q];
        acc.x += ex0 * ra.x + ex1 * rb.x + ex2 * rc.x + ex3 * rd.x;
        acc.y += ex0 * ra.y + ex1 * rb.y + ex2 * rc.y + ex3 * rd.y;
        acc.z += ex0 * ra.z + ex1 * rb.z + ex2 * rc.z + ex3 * rd.z;
        acc.w += ex0 * ra.w + ex1 * rb.w + ex2 * rc.w + ex3 * rd.w;
    }
    reinterpret_cast<float4*>(d_hga)[g * 16 + q] = acc;
}

// SAGE gather (CSR): mean[g] = sum_{r in in(g)} relu(hga[r]+bg)
__global__ void k_sage_gather(const float* __restrict__ bg, int n) {
    int g = blockIdx.x * 16 + (threadIdx.x >> 4);
    int q = threadIdx.x & 15;
    if (g >= n) return;
    float4 bv = __ldg(reinterpret_cast<const float4*>(bg) + q);
    float4 acc = make_float4(0.f, 0.f, 0.f, 0.f);
    int o0 = d_off[g], o1 = d_off[g + 1];
    for (int o = o0; o < o1; o++) {
        int r = __ldg(&d_epack[o].x);
        float4 h = __ldg(reinterpret_cast<const float4*>(d_hga) + r * 16 + q);
        acc.x += fmaxf(h.x + bv.x, 0.f);
        acc.y += fmaxf(h.y + bv.y, 0.f);
        acc.z += fmaxf(h.z + bv.z, 0.f);
        acc.w += fmaxf(h.w + bv.w, 0.f);
    }
    reinterpret_cast<float4*>(d_mean)[g * 16 + q] = acc;
}

// final: emb = (mean/deg)@Wl + bl + relu(hga+bg)@Wr ; MLP heads ; outputs
__global__ void k_final(const float* __restrict__ Wl, const float* __restrict__ bl,
                        const float* __restrict__ Wr, const float* __restrict__ bg,
                        const float* __restrict__ a1w, const float* __restrict__ a1b,
                        const float* __restrict__ a2w, const float* __restrict__ a2b,
                        const float* __restrict__ r1w, const float* __restrict__ r1b,
                        const float* __restrict__ r2w, const float* __restrict__ r2b,
                        float* __restrict__ out_emb, float* __restrict__ out_an,
                        float* __restrict__ out_risk, int n) {
    __shared__ float Wls[HD * HD], Wrs[HD * HD];
    __shared__ float ms[4][HD], hs[4][HD], embs[4][HD];
    int tid = threadIdx.x;
    for (int i = tid; i < HD * HD; i += blockDim.x) {
        Wls[i] = Wl[i];
        Wrs[i] = Wr[i];
    }
    int sub = tid >> 6, j = tid & 63;
    int lane = tid & 31, wp = tid >> 5;
    int nd = wp >> 1, hd = wp & 1;
    for (long long base = (long long)blockIdx.x * 4; base < n;
         base += (long long)gridDim.x * 4) {
        int node = (int)base + sub;
        __syncthreads();
        if (node < n) {
            float inv = 1.f / fmaxf((float)d_deg[node], 1.f);
            ms[sub][j] = d_mean[node * HD + j] * inv;
            hs[sub][j] = fmaxf(d_hga[node * HD + j] + bg[j], 0.f);
        }
        __syncthreads();
        if (node < n) {
            float acc = bl[j];
#pragma unroll 16
            for (int k = 0; k < HD; k++)
                acc += ms[sub][k] * Wls[k * HD + j] + hs[sub][k] * Wrs[k * HD + j];
            embs[sub][j] = acc;
            out_emb[(long long)node * HD + j] = acc;
        }
        __syncthreads();
        int node2 = (int)base + nd;
        if (node2 < n) {
            const float* W1p = hd ? r1w : a1w;
            float acc = hd ? __ldg(&r1b[lane]) : __ldg(&a1b[lane]);
#pragma unroll 16
            for (int k = 0; k < HD; k++)
                acc += embs[nd][k] * __ldg(&W1p[k * 32 + lane]);
            acc = fmaxf(acc, 0.f) * (hd ? __ldg(&r2w[lane]) : __ldg(&a2w[lane]));
#pragma unroll
            for (int o = 16; o; o >>= 1) acc += __shfl_down_sync(0xffffffffu, acc, o);
            if (lane == 0) {
                float b2 = hd ? __ldg(&r2b[0]) : __ldg(&a2b[0]);
                float v = 1.f / (1.f + expf(-(acc + b2)));
                if (hd) out_risk[node2] = v;
                else    out_an[node2] = v;
            }
        }
    }
}

// ---------------- launcher ----------------
extern "C" void kernel_launch(void* const* d_in, const int* in_sizes, int n_in,
                              void* d_out, int out_size) {
    const float* x   = (const float*)d_in[0];
    const int*   ei  = (const int*)d_in[1];   // int32 (JAX x64 disabled)
    const float* W1  = (const float*)d_in[2];
    const float* b1  = (const float*)d_in[3];
    const float* Wg  = (const float*)d_in[4];
    const float* ats = (const float*)d_in[5];
    const float* atd = (const float*)d_in[6];
    const float* bg  = (const float*)d_in[7];
    const float* Wl  = (const float*)d_in[8];
    const float* bl  = (const float*)d_in[9];
    const float* Wr  = (const float*)d_in[10];
    const float* a1w = (const float*)d_in[11];
    const float* a1b = (const float*)d_in[12];
    const float* a2w = (const float*)d_in[13];
    const float* a2b = (const float*)d_in[14];
    const float* r1w = (const float*)d_in[15];
    const float* r1b = (const float*)d_in[16];
    const float* r2w = (const float*)d_in[17];
    const float* r2b = (const float*)d_in[18];

    int n = in_sizes[0] / FIN;
    int e = in_sizes[1] / 2;
    const int* row0 = ei;
    const int* col0 = ei + e;

    float* out      = (float*)d_out;
    float* out_emb  = out;
    float* out_an   = out + (long long)n * HD;
    float* out_risk = out_an + n;

    const int B = 256;
    int gN  = (n + B - 1) / B;
    int gE  = (e + B - 1) / B;
    int gG  = (n + 15) / 16;

    // CSR build
    k_zero_deg<<<gN, B>>>(n);
    k_count<<<gE, B>>>(col0, e, n);
    k_scan<<<1, 1024>>>(n);
    k_fill<<<gE, B>>>(row0, col0, e, n);

    // GCN
    k_gemm_gcn<<<(n + 63) / 64, 256>>>(x, W1, n);
    k_gcn_gather<<<gG, B>>>(n);

    // GAT
    k_gemm_gat<<<(n + 31) / 32, 256>>>(Wg, b1, n);
    k_att<<<(n * NHEADS * 32 + B - 1) / B, B>>>(ats, atd, n);
    k_den_edges<<<gE, B>>>(row0, col0, e, n);
    k_gat_gather<<<gG, B>>>(n);

    // SAGE
    k_sage_gather<<<gG, B>>>(bg, n);

    // emb + heads
    k_final<<<(n + 3) / 4, B>>>(Wl, bl, Wr, bg, a1w, a1b, a2w, a2b,
                                r1w, r1b, r2w, r2b,
                                out_emb, out_an, out_risk, n);
}

// round 17
// speedup vs baseline: 1.7678x; 1.1255x over previous
#include <cuda_runtime.h>

#define NMAX 50000
#define EMAX 800000
#define HD   64
#define FIN  128
#define NHEADS 4

// ---------------- scratch (static device memory; no allocs) ----------------
__device__ __align__(16) float d_h   [NMAX * HD];          // dinv-scaled xW1 (gather src)
__device__ __align__(16) float d_h2  [NMAX * HD];          // GCN gather result
__device__ __align__(16) float d_hg  [NMAX * NHEADS * HD]; // GAT features [N,4,64]
__device__ __align__(16) float d_asrc[NMAX * NHEADS];
__device__ __align__(16) float d_adst[NMAX * NHEADS];
__device__ __align__(16) float d_den [NMAX * NHEADS];      // softmax denom (raw sums)
__device__ __align__(16) float d_alpha[EMAX * NHEADS];     // per-edge exp values
__device__ __align__(16) float d_hga [NMAX * HD];          // GAT aggregation
__device__ __align__(16) float d_mean[NMAX * HD];          // SAGE sums
__device__ float d_dinv[NMAX];                             // rsqrt(deg+1)
__device__ int   d_deg [NMAX];                             // in-degree (no self loops)
__device__ int   d_off [NMAX + 1];                         // CSR offsets
__device__ int   d_pos [NMAX];                             // fill cursors
__device__ int2  d_epack[EMAX];                            // CSR entries {src, edge id}
__device__ int   d_row32[EMAX];
__device__ int   d_col32[EMAX];

// ---------------- helpers ----------------
__device__ __forceinline__ float lrelu(float x) { return x > 0.f ? x : 0.2f * x; }

__device__ __forceinline__ void red_add_v4(float4* p, float4 v) {
    asm volatile("red.global.add.v4.f32 [%0], {%1, %2, %3, %4};"
                 :: "l"(p), "f"(v.x), "f"(v.y), "f"(v.z), "f"(v.w) : "memory");
}

// ---------------- CSR construction ----------------

__global__ void k_zero0(int n) {
    int i = blockIdx.x * blockDim.x + threadIdx.x;
    if (i < n) { d_deg[i] = 0; d_pos[i] = 0; }
}

// edge_index is INT32 (JAX x64 disabled). Copy + validate + in-degree count.
__global__ void k_edges32(const int* __restrict__ row0,
                          const int* __restrict__ col0, int e, int n) {
    int i = blockIdx.x * blockDim.x + threadIdx.x;
    if (i < e) {
        int r = row0[i];
        int c = col0[i];
        if ((unsigned)r >= (unsigned)n) r = 0;
        if ((unsigned)c >= (unsigned)n) c = 0;
        d_row32[i] = r;
        d_col32[i] = c;
        atomicAdd(&d_deg[c], 1);
    }
}

// single-block exclusive scan of d_deg -> d_off (n up to NMAX)
__global__ void __launch_bounds__(1024) k_scan(int n) {
    __shared__ int ss[1024];
    int tid = threadIdx.x;
    int per = (n + 1023) >> 10;
    int start = tid * per;
    int end = min(start + per, n);
    int s = 0;
    for (int i = start; i < end; i++) s += d_deg[i];
    ss[tid] = s;
    __syncthreads();
    for (int off = 1; off < 1024; off <<= 1) {
        int v = (tid >= off) ? ss[tid - off] : 0;
        __syncthreads();
        ss[tid] += v;
        __syncthreads();
    }
    int run = (tid == 0) ? 0 : ss[tid - 1];
    for (int i = start; i < end; i++) {
        d_off[i] = run;
        run += d_deg[i];
    }
    if (tid == 1023) d_off[n] = run;
}

__global__ void k_fill(int e) {
    int i = blockIdx.x * blockDim.x + threadIdx.x;
    if (i < e) {
        int r = d_row32[i], c = d_col32[i];
        int slot = atomicAdd(&d_pos[c], 1);
        d_epack[d_off[c] + slot] = make_int2(r, i);
    }
}

__global__ void k_dinv(int n) {
    int i = blockIdx.x * blockDim.x + threadIdx.x;
    if (i < n) d_dinv[i] = rsqrtf((float)d_deg[i] + 1.0f);
}

// ---------------- GCN GEMM: d_h = dinv[row]*(x@W1) ----------------
__global__ void k_gemm_gcn(const float* __restrict__ A, const float* __restrict__ W, int n) {
    const int K = FIN, JT = 16, SG = 16, RPT = 4;
    const int ROWS = SG * RPT;                       // 64
    __shared__ float xs[ROWS][K];
    int tid = threadIdx.x;
    int j0  = tid % JT;
    int sg  = tid / JT;
    long long base = (long long)blockIdx.x * ROWS;
    {
        const int T4 = ROWS * (K / 4);
        for (int i4 = tid; i4 < T4; i4 += 256) {
            long long row = base + i4 / (K / 4);
            int col4 = i4 % (K / 4);
            reinterpret_cast<float4*>(xs)[i4] =
                (row < n) ? __ldg(reinterpret_cast<const float4*>(A + row * K) + col4)
                          : make_float4(0.f, 0.f, 0.f, 0.f);
        }
    }
    __syncthreads();
    float4 acc[RPT];
#pragma unroll
    for (int r = 0; r < RPT; r++) acc[r] = make_float4(0.f, 0.f, 0.f, 0.f);
#pragma unroll 4
    for (int k = 0; k < K; k++) {
        float4 wv = __ldg(reinterpret_cast<const float4*>(W + k * HD) + j0);
#pragma unroll
        for (int r = 0; r < RPT; r++) {
            float xv = xs[sg * RPT + r][k];
            acc[r].x += xv * wv.x;
            acc[r].y += xv * wv.y;
            acc[r].z += xv * wv.z;
            acc[r].w += xv * wv.w;
        }
    }
#pragma unroll
    for (int r = 0; r < RPT; r++) {
        long long row = base + sg * RPT + r;
        if (row < n) {
            float dv = __ldg(&d_dinv[row]);
            reinterpret_cast<float4*>(d_h)[row * 16 + j0] =
                make_float4(acc[r].x * dv, acc[r].y * dv, acc[r].z * dv, acc[r].w * dv);
        }
    }
}

// GCN gather (CSR): h2[g] = h[g] + sum_{r in in(g)} h[r]   (no atomics)
__global__ void k_gcn_gather(int n) {
    int g = blockIdx.x * 16 + (threadIdx.x >> 4);
    int q = threadIdx.x & 15;
    if (g >= n) return;
    int o0 = d_off[g], o1 = d_off[g + 1];
    float4 acc = reinterpret_cast<const float4*>(d_h)[g * 16 + q];
    for (int o = o0; o < o1; o++) {
        int r = __ldg(&d_epack[o].x);
        float4 v = __ldg(reinterpret_cast<const float4*>(d_h) + r * 16 + q);
        acc.x += v.x; acc.y += v.y; acc.z += v.z; acc.w += v.w;
    }
    reinterpret_cast<float4*>(d_h2)[g * 16 + q] = acc;
}

// ---------------- GAT GEMM (fused relu(dinv*h2+b1)) ----------------
__global__ void k_gemm_gat(const float* __restrict__ Wg, const float* __restrict__ b1, int n) {
    const int K = HD, M = NHEADS * HD, JT = 64, SG = 4, RPT = 8;
    const int ROWS = SG * RPT;                       // 32
    __shared__ float xs[ROWS][K];
    int tid = threadIdx.x;
    int j0  = tid % JT;
    int sg  = tid / JT;
    long long base = (long long)blockIdx.x * ROWS;
    {
        const int T4 = ROWS * (K / 4);
        for (int i4 = tid; i4 < T4; i4 += 256) {
            long long row = base + i4 / (K / 4);
            int col4 = i4 % (K / 4);
            float4 v = make_float4(0.f, 0.f, 0.f, 0.f);
            if (row < n) {
                float4 h2v = __ldg(reinterpret_cast<const float4*>(d_h2) + row * 16 + col4);
                float4 bv  = __ldg(reinterpret_cast<const float4*>(b1) + col4);
                float dv = __ldg(&d_dinv[row]);
                v.x = fmaxf(dv * h2v.x + bv.x, 0.f);
                v.y = fmaxf(dv * h2v.y + bv.y, 0.f);
                v.z = fmaxf(dv * h2v.z + bv.z, 0.f);
                v.w = fmaxf(dv * h2v.w + bv.w, 0.f);
            }
            reinterpret_cast<float4*>(xs)[i4] = v;
        }
    }
    __syncthreads();
    float4 acc[RPT];
#pragma unroll
    for (int r = 0; r < RPT; r++) acc[r] = make_float4(0.f, 0.f, 0.f, 0.f);
#pragma unroll 4
    for (int k = 0; k < K; k++) {
        float4 wv = __ldg(reinterpret_cast<const float4*>(Wg + k * M) + j0);
#pragma unroll
        for (int r = 0; r < RPT; r++) {
            float xv = xs[sg * RPT + r][k];
            acc[r].x += xv * wv.x;
            acc[r].y += xv * wv.y;
            acc[r].z += xv * wv.z;
            acc[r].w += xv * wv.w;
        }
    }
#pragma unroll
    for (int r = 0; r < RPT; r++) {
        long long row = base + sg * RPT + r;
        if (row < n)
            reinterpret_cast<float4*>(d_hg)[row * 64 + j0] = acc[r];
    }
}

// per-(node,head) attention logits + denom init = exp(self logit)
__global__ void k_att(const float* __restrict__ att_src,
                      const float* __restrict__ att_dst, int n) {
    long long w = (long long)(blockIdx.x * blockDim.x + threadIdx.x) >> 5;
    int lane = threadIdx.x & 31;
    long long total = (long long)n * NHEADS;
    long long stride = ((long long)gridDim.x * blockDim.x) >> 5;
    for (; w < total; w += stride) {
        int node = (int)(w >> 2), head = (int)(w & 3);
        const float* hgp = &d_hg[(long long)node * (NHEADS * HD) + head * HD];
        float s = hgp[lane] * __ldg(&att_src[head * HD + lane]) +
                  hgp[lane + 32] * __ldg(&att_src[head * HD + lane + 32]);
        float t = hgp[lane] * __ldg(&att_dst[head * HD + lane]) +
                  hgp[lane + 32] * __ldg(&att_dst[head * HD + lane + 32]);
#pragma unroll
        for (int o = 16; o; o >>= 1) {
            s += __shfl_down_sync(0xffffffffu, s, o);
            t += __shfl_down_sync(0xffffffffu, t, o);
        }
        if (lane == 0) {
            d_asrc[w] = s;
            d_adst[w] = t;
            d_den[w]  = expf(lrelu(s + t));
        }
    }
}

// per-edge ex = exp(lrelu(asrc[r]+adst[c])): store + vector-RED into denom
__global__ void k_den_edges(int e) {
    int i = blockIdx.x * blockDim.x + threadIdx.x;
    if (i < e) {
        int r = d_row32[i], c = d_col32[i];
        const float4 as = reinterpret_cast<const float4*>(d_asrc)[r];
        const float4 ad = reinterpret_cast<const float4*>(d_adst)[c];
        float4 ex;
        ex.x = expf(lrelu(as.x + ad.x));
        ex.y = expf(lrelu(as.y + ad.y));
        ex.z = expf(lrelu(as.z + ad.z));
        ex.w = expf(lrelu(as.w + ad.w));
        reinterpret_cast<float4*>(d_alpha)[i] = ex;
        red_add_v4(&reinterpret_cast<float4*>(d_den)[c], ex);
    }
}

// GAT gather (CSR): hga[g] = sum over {self, in-edges} of per-head weighted hg rows
__global__ void k_gat_gather(int n) {
    int g = blockIdx.x * 16 + (threadIdx.x >> 4);
    int q = threadIdx.x & 15;
    if (g >= n) return;
    const float4 dn = reinterpret_cast<const float4*>(d_den)[g];
    float ix = 0.25f / dn.x, iy = 0.25f / dn.y, iz = 0.25f / dn.z, iw = 0.25f / dn.w;
    const float4 as = reinterpret_cast<const float4*>(d_asrc)[g];
    const float4 ad = reinterpret_cast<const float4*>(d_adst)[g];
    float wx = expf(lrelu(as.x + ad.x)) * ix;
    float wy = expf(lrelu(as.y + ad.y)) * iy;
    float wz = expf(lrelu(as.z + ad.z)) * iz;
    float ww = expf(lrelu(as.w + ad.w)) * iw;
    const float4* hg4 = reinterpret_cast<const float4*>(d_hg);
    long long sbase = (long long)g * 64;
    float4 a = hg4[sbase + 0 * 16 + q];
    float4 b = hg4[sbase + 1 * 16 + q];
    float4 cc = hg4[sbase + 2 * 16 + q];
    float4 dd = hg4[sbase + 3 * 16 + q];
    float4 acc;
    acc.x = wx * a.x + wy * b.x + wz * cc.x + ww * dd.x;
    acc.y = wx * a.y + wy * b.y + wz * cc.y + ww * dd.y;
    acc.z = wx * a.z + wy * b.z + wz * cc.z + ww * dd.z;
    acc.w = wx * a.w + wy * b.w + wz * cc.w + ww * dd.w;
    int o0 = d_off[g], o1 = d_off[g + 1];
    for (int o = o0; o < o1; o++) {
        int2 pk = __ldg(&d_epack[o]);
        const float4 ex = __ldg(reinterpret_cast<const float4*>(d_alpha) + pk.y);
        float ex0 = ex.x * ix, ex1 = ex.y * iy, ex2 = ex.z * iz, ex3 = ex.w * iw;
        long long base = (long long)pk.x * 64;
        float4 ra = hg4[base + 0 * 16 + q];
        float4 rb = hg4[base + 1 * 16 + q];
        float4 rc = hg4[base + 2 * 16 + q];
        float4 rd = hg4[base + 3 * 16 + q];
        acc.x += ex0 * ra.x + ex1 * rb.x + ex2 * rc.x + ex3 * rd.x;
        acc.y += ex0 * ra.y + ex1 * rb.y + ex2 * rc.y + ex3 * rd.y;
        acc.z += ex0 * ra.z + ex1 * rb.z + ex2 * rc.z + ex3 * rd.z;
        acc.w += ex0 * ra.w + ex1 * rb.w + ex2 * rc.w + ex3 * rd.w;
    }
    reinterpret_cast<float4*>(d_hga)[g * 16 + q] = acc;
}

// SAGE gather (CSR): mean[g] = sum_{r in in(g)} relu(hga[r]+bg)
__global__ void k_sage_gather(const float* __restrict__ bg, int n) {
    int g = blockIdx.x * 16 + (threadIdx.x >> 4);
    int q = threadIdx.x & 15;
    if (g >= n) return;
    float4 bv = __ldg(reinterpret_cast<const float4*>(bg) + q);
    float4 acc = make_float4(0.f, 0.f, 0.f, 0.f);
    int o0 = d_off[g], o1 = d_off[g + 1];
    for (int o = o0; o < o1; o++) {
        int r = __ldg(&d_epack[o].x);
        float4 h = __ldg(reinterpret_cast<const float4*>(d_hga) + r * 16 + q);
        acc.x += fmaxf(h.x + bv.x, 0.f);
        acc.y += fmaxf(h.y + bv.y, 0.f);
        acc.z += fmaxf(h.z + bv.z, 0.f);
        acc.w += fmaxf(h.w + bv.w, 0.f);
    }
    reinterpret_cast<float4*>(d_mean)[g * 16 + q] = acc;
}

// final: emb = (mean/deg)@Wl + bl + relu(hga+bg)@Wr ; MLP heads ; outputs
__global__ void k_final(const float* __restrict__ Wl, const float* __restrict__ bl,
                        const float* __restrict__ Wr, const float* __restrict__ bg,
                        const float* __restrict__ a1w, const float* __restrict__ a1b,
                        const float* __restrict__ a2w, const float* __restrict__ a2b,
                        const float* __restrict__ r1w, const float* __restrict__ r1b,
                        const float* __restrict__ r2w, const float* __restrict__ r2b,
                        float* __restrict__ out_emb, float* __restrict__ out_an,
                        float* __restrict__ out_risk, int n) {
    __shared__ float Wls[HD * HD], Wrs[HD * HD];
    __shared__ float ms[4][HD], hs[4][HD], embs[4][HD];
    int tid = threadIdx.x;
    for (int i = tid; i < HD * HD; i += blockDim.x) {
        Wls[i] = Wl[i];
        Wrs[i] = Wr[i];
    }
    int sub = tid >> 6, j = tid & 63;
    int lane = tid & 31, wp = tid >> 5;
    int nd = wp >> 1, hd = wp & 1;
    for (long long base = (long long)blockIdx.x * 4; base < n;
         base += (long long)gridDim.x * 4) {
        int node = (int)base + sub;
        __syncthreads();
        if (node < n) {
            float inv = 1.f / fmaxf((float)d_deg[node], 1.f);
            ms[sub][j] = d_mean[node * HD + j] * inv;
            hs[sub][j] = fmaxf(d_hga[node * HD + j] + bg[j], 0.f);
        }
        __syncthreads();
        if (node < n) {
            float acc = bl[j];
#pragma unroll 16
            for (int k = 0; k < HD; k++)
                acc += ms[sub][k] * Wls[k * HD + j] + hs[sub][k] * Wrs[k * HD + j];
            embs[sub][j] = acc;
            out_emb[(long long)node * HD + j] = acc;
        }
        __syncthreads();
        int node2 = (int)base + nd;
        if (node2 < n) {
            const float* W1p = hd ? r1w : a1w;
            float acc = hd ? __ldg(&r1b[lane]) : __ldg(&a1b[lane]);
#pragma unroll 16
            for (int k = 0; k < HD; k++)
                acc += embs[nd][k] * __ldg(&W1p[k * 32 + lane]);
            acc = fmaxf(acc, 0.f) * (hd ? __ldg(&r2w[lane]) : __ldg(&a2w[lane]));
#pragma unroll
            for (int o = 16; o; o >>= 1) acc += __shfl_down_sync(0xffffffffu, acc, o);
            if (lane == 0) {
                float b2 = hd ? __ldg(&r2b[0]) : __ldg(&a2b[0]);
                float v = 1.f / (1.f + expf(-(acc + b2)));
                if (hd) out_risk[node2] = v;
                else    out_an[node2] = v;
            }
        }
    }
}

// ---------------- launcher ----------------
extern "C" void kernel_launch(void* const* d_in, const int* in_sizes, int n_in,
                              void* d_out, int out_size) {
    const float* x   = (const float*)d_in[0];
    const int*   ei  = (const int*)d_in[1];   // int32 (JAX x64 disabled)
    const float* W1  = (const float*)d_in[2];
    const float* b1  = (const float*)d_in[3];
    const float* Wg  = (const float*)d_in[4];
    const float* ats = (const float*)d_in[5];
    const float* atd = (const float*)d_in[6];
    const float* bg  = (const float*)d_in[7];
    const float* Wl  = (const float*)d_in[8];
    const float* bl  = (const float*)d_in[9];
    const float* Wr  = (const float*)d_in[10];
    const float* a1w = (const float*)d_in[11];
    const float* a1b = (const float*)d_in[12];
    const float* a2w = (const float*)d_in[13];
    const float* a2b = (const float*)d_in[14];
    const float* r1w = (const float*)d_in[15];
    const float* r1b = (const float*)d_in[16];
    const float* r2w = (const float*)d_in[17];
    const float* r2b = (const float*)d_in[18];

    int n = in_sizes[0] / FIN;
    int e = in_sizes[1] / 2;
    const int* row0 = ei;
    const int* col0 = ei + e;

    float* out      = (float*)d_out;
    float* out_emb  = out;
    float* out_an   = out + (long long)n * HD;
    float* out_risk = out_an + n;

    const int B = 256;
    int gN  = (n + B - 1) / B;
    int gE  = (e + B - 1) / B;
    int gG  = (n + 15) / 16;

    // CSR build
    k_zero0<<<gN, B>>>(n);
    k_edges32<<<gE, B>>>(row0, col0, e, n);
    k_scan<<<1, 1024>>>(n);
    k_fill<<<gE, B>>>(e);
    k_dinv<<<gN, B>>>(n);

    // GCN
    k_gemm_gcn<<<(n + 63) / 64, 256>>>(x, W1, n);
    k_gcn_gather<<<gG, B>>>(n);

    // GAT
    k_gemm_gat<<<(n + 31) / 32, 256>>>(Wg, b1, n);
    k_att<<<(n * NHEADS * 32 + B - 1) / B, B>>>(ats, atd, n);
    k_den_edges<<<gE, B>>>(e);
    k_gat_gather<<<gG, B>>>(n);

    // SAGE
    k_sage_gather<<<gG, B>>>(bg, n);

    // emb + heads
    k_final<<<(n + 3) / 4, B>>>(Wl, bl, Wr, bg, a1w, a1b, a2w, a2b,
                                r1w, r1b, r2w, r2b,
                                out_emb, out_an, out_risk, n);
}